// round 11
// baseline (speedup 1.0000x reference)
#include <cuda_runtime.h>

#define NN 50000
#define EE 800000
#define HID 128
#define EIN 64

// ---------------- scratch (device globals: no allocation allowed) ----------
__device__ float g_x0[NN * HID];
__device__ float g_x1[NN * HID];
__device__ float g_aggr[NN * HID];
__device__ float g_U[NN * HID];
__device__ float g_V[NN * HID];
__device__ int g_src[EE];
__device__ int g_dst[EE];
__device__ int g_found;

// ---------------- edge_index dtype detection + conversion ------------------
__global__ void init_flag_kernel() { g_found = 0; }

// If edge_index is int64 (little-endian, values < 2^31), every odd 32-bit
// word of the first 2*EE words is a zero high-half. If int32, odd words are
// random indices in [0, 50000) -> virtually guaranteed nonzero somewhere.
__global__ void detect_kernel(const unsigned int* __restrict__ w) {
    unsigned int acc = 0;
    long long stride = (long long)gridDim.x * blockDim.x;
    long long i = (long long)blockIdx.x * blockDim.x + threadIdx.x;
    for (long long j = 2 * i + 1; j < 2LL * EE; j += 2 * stride) acc |= w[j];
    if (acc) g_found = 1;  // idempotent plain store
}

__global__ void convert_kernel(const void* __restrict__ ei) {
    int i = blockIdx.x * blockDim.x + threadIdx.x;
    int stride = gridDim.x * blockDim.x;
    if (g_found) {  // int32 layout
        const int* p = (const int*)ei;
        for (; i < EE; i += stride) { g_src[i] = p[i]; g_dst[i] = p[EE + i]; }
    } else {        // int64 layout
        const long long* p = (const long long*)ei;
        for (; i < EE; i += stride) { g_src[i] = (int)p[i]; g_dst[i] = (int)p[EE + i]; }
    }
}

__global__ void zero_aggr_kernel() {
    int i = blockIdx.x * blockDim.x + threadIdx.x;
    int stride = gridDim.x * blockDim.x;
    float4 z = make_float4(0.f, 0.f, 0.f, 0.f);
    float4* p = (float4*)g_aggr;
    for (; i < NN * HID / 4; i += stride) p[i] = z;
}

// ---------------- fused GINE message + aggregate ----------------------------
// e = edge_attr @ W_l + b_l ; m = relu(x[src] + e) ; aggr[dst] += m
// Block = 256 threads (8 warps), 64 edges per tile, 8 edges per warp.
// W_l (64x128) + bias + 64 edge_attr rows staged in smem.
__global__ void __launch_bounds__(256) edge_kernel(
    const float* __restrict__ xin,
    const float* __restrict__ eattr,
    const float* __restrict__ W,
    const float* __restrict__ b)
{
    extern __shared__ float sm[];
    float* sW  = sm;                  // 64*128 = 8192 floats
    float* sb  = sW + EIN * HID;      // 128 floats
    float* sea = sb + HID;            // 64*64 = 4096 floats

    int tid = threadIdx.x;
    for (int i = tid; i < EIN * HID / 4; i += 256)
        ((float4*)sW)[i] = ((const float4*)W)[i];
    if (tid < HID / 4)
        ((float4*)sb)[tid] = ((const float4*)b)[tid];
    __syncthreads();

    int w = tid >> 5, lane = tid & 31;
    float4 bia = ((float4*)sb)[lane];
    const float* myea = sea + w * 8 * EIN;

    const int ntiles = EE / 64;  // 800000/64 = 12500, exact
    for (int t = blockIdx.x; t < ntiles; t += gridDim.x) {
        __syncthreads();  // protect sea from previous iteration's readers
        const float4* g4 = (const float4*)(eattr + (size_t)t * 64 * EIN);
        for (int i = tid; i < 64 * EIN / 4; i += 256) ((float4*)sea)[i] = g4[i];
        __syncthreads();

        float4 acc[8];
        #pragma unroll
        for (int j = 0; j < 8; j++) acc[j] = bia;

        #pragma unroll 2
        for (int k = 0; k < EIN; k++) {
            float4 wv = ((const float4*)(sW + k * HID))[lane];
            #pragma unroll
            for (int j = 0; j < 8; j++) {
                float a = myea[j * EIN + k];  // smem broadcast
                acc[j].x = fmaf(a, wv.x, acc[j].x);
                acc[j].y = fmaf(a, wv.y, acc[j].y);
                acc[j].z = fmaf(a, wv.z, acc[j].z);
                acc[j].w = fmaf(a, wv.w, acc[j].w);
            }
        }

        int ebase = t * 64 + w * 8;
        #pragma unroll
        for (int j = 0; j < 8; j++) {
            int e = ebase + j;
            int s = g_src[e], d = g_dst[e];
            float4 xv = ((const float4*)(xin + (size_t)s * HID))[lane];  // L2-resident gather
            float m0 = fmaxf(acc[j].x + xv.x, 0.f);
            float m1 = fmaxf(acc[j].y + xv.y, 0.f);
            float m2 = fmaxf(acc[j].z + xv.z, 0.f);
            float m3 = fmaxf(acc[j].w + xv.w, 0.f);
            float* ap = g_aggr + (size_t)d * HID + 4 * lane;
            atomicAdd(ap + 0, m0);
            atomicAdd(ap + 1, m1);
            atomicAdd(ap + 2, m2);
            atomicAdd(ap + 3, m3);
        }
    }
}

// ---------------- fused GIN node MLP ----------------------------------------
// h = x + aggr ; x_new = relu( relu(h@W1 + b1) @ W2 + b2 )
// Both 128x128 weight matrices in smem; 4 nodes per warp, 32 nodes per tile.
__global__ void __launch_bounds__(256) node_kernel(
    const float* __restrict__ xin,
    const float* __restrict__ W1, const float* __restrict__ b1,
    const float* __restrict__ W2, const float* __restrict__ b2,
    float* __restrict__ xout)
{
    extern __shared__ float sm[];
    float* sW1 = sm;                    // 16384
    float* sW2 = sW1 + HID * HID;       // 16384
    float* sb1 = sW2 + HID * HID;       // 128
    float* sb2 = sb1 + HID;             // 128
    float* sh  = sb2 + HID;             // 8 warps * 4 nodes * 128 = 4096

    int tid = threadIdx.x;
    for (int i = tid; i < HID * HID / 4; i += 256) {
        ((float4*)sW1)[i] = ((const float4*)W1)[i];
        ((float4*)sW2)[i] = ((const float4*)W2)[i];
    }
    if (tid < HID / 4) {
        ((float4*)sb1)[tid] = ((const float4*)b1)[tid];
        ((float4*)sb2)[tid] = ((const float4*)b2)[tid];
    }
    __syncthreads();

    int w = tid >> 5, lane = tid & 31;
    float4 b1v = ((float4*)sb1)[lane];
    float4 b2v = ((float4*)sb2)[lane];
    float* myh = sh + w * 4 * HID;

    const int ntiles = (NN + 31) / 32;
    for (int t = blockIdx.x; t < ntiles; t += gridDim.x) {
        int nbase = t * 32 + w * 4;
        __syncwarp();
        #pragma unroll
        for (int j = 0; j < 4; j++) {
            int n = nbase + j;
            float4 hv = make_float4(0.f, 0.f, 0.f, 0.f);
            if (n < NN) {
                float4 xv = ((const float4*)(xin    + (size_t)n * HID))[lane];
                float4 av = ((const float4*)(g_aggr + (size_t)n * HID))[lane];
                hv.x = xv.x + av.x; hv.y = xv.y + av.y;
                hv.z = xv.z + av.z; hv.w = xv.w + av.w;
            }
            ((float4*)(myh + j * HID))[lane] = hv;
        }
        __syncwarp();

        float4 acc[4];
        #pragma unroll
        for (int j = 0; j < 4; j++) acc[j] = b1v;
        #pragma unroll 2
        for (int k = 0; k < HID; k++) {
            float4 wv = ((const float4*)(sW1 + k * HID))[lane];
            #pragma unroll
            for (int j = 0; j < 4; j++) {
                float a = myh[j * HID + k];
                acc[j].x = fmaf(a, wv.x, acc[j].x);
                acc[j].y = fmaf(a, wv.y, acc[j].y);
                acc[j].z = fmaf(a, wv.z, acc[j].z);
                acc[j].w = fmaf(a, wv.w, acc[j].w);
            }
        }
        __syncwarp();  // all reads of myh done before overwrite
        #pragma unroll
        for (int j = 0; j < 4; j++) {
            float4 tv;
            tv.x = fmaxf(acc[j].x, 0.f); tv.y = fmaxf(acc[j].y, 0.f);
            tv.z = fmaxf(acc[j].z, 0.f); tv.w = fmaxf(acc[j].w, 0.f);
            ((float4*)(myh + j * HID))[lane] = tv;
        }
        __syncwarp();

        #pragma unroll
        for (int j = 0; j < 4; j++) acc[j] = b2v;
        #pragma unroll 2
        for (int k = 0; k < HID; k++) {
            float4 wv = ((const float4*)(sW2 + k * HID))[lane];
            #pragma unroll
            for (int j = 0; j < 4; j++) {
                float a = myh[j * HID + k];
                acc[j].x = fmaf(a, wv.x, acc[j].x);
                acc[j].y = fmaf(a, wv.y, acc[j].y);
                acc[j].z = fmaf(a, wv.z, acc[j].z);
                acc[j].w = fmaf(a, wv.w, acc[j].w);
            }
        }
        #pragma unroll
        for (int j = 0; j < 4; j++) {
            int n = nbase + j;
            if (n < NN) {
                float4 ov;
                ov.x = fmaxf(acc[j].x, 0.f); ov.y = fmaxf(acc[j].y, 0.f);
                ov.z = fmaxf(acc[j].z, 0.f); ov.w = fmaxf(acc[j].w, 0.f);
                ((float4*)(xout + (size_t)n * HID))[lane] = ov;
            }
        }
    }
}

// ---------------- predictor factorization: U = x@A + pb1, V = x@B -----------
// A = pW1[0:128,:], B = pW1[128:256,:]
__global__ void __launch_bounds__(256) uv_kernel(
    const float* __restrict__ xin,
    const float* __restrict__ pW1, const float* __restrict__ pb1)
{
    extern __shared__ float sm[];
    float* sA = sm;                 // 16384
    float* sB = sA + HID * HID;     // 16384
    float* sb = sB + HID * HID;     // 128
    float* sh = sb + HID;           // 4096

    int tid = threadIdx.x;
    for (int i = tid; i < HID * HID / 4; i += 256) {
        ((float4*)sA)[i] = ((const float4*)pW1)[i];
        ((float4*)sB)[i] = ((const float4*)(pW1 + HID * HID))[i];
    }
    if (tid < HID / 4) ((float4*)sb)[tid] = ((const float4*)pb1)[tid];
    __syncthreads();

    int w = tid >> 5, lane = tid & 31;
    float4 bv = ((float4*)sb)[lane];
    float* myh = sh + w * 4 * HID;

    const int ntiles = (NN + 31) / 32;
    for (int t = blockIdx.x; t < ntiles; t += gridDim.x) {
        int nbase = t * 32 + w * 4;
        __syncwarp();
        #pragma unroll
        for (int j = 0; j < 4; j++) {
            int n = nbase + j;
            float4 hv = make_float4(0.f, 0.f, 0.f, 0.f);
            if (n < NN) hv = ((const float4*)(xin + (size_t)n * HID))[lane];
            ((float4*)(myh + j * HID))[lane] = hv;
        }
        __syncwarp();

        float4 aU[4], aV[4];
        #pragma unroll
        for (int j = 0; j < 4; j++) {
            aU[j] = bv;
            aV[j] = make_float4(0.f, 0.f, 0.f, 0.f);
        }
        #pragma unroll 2
        for (int k = 0; k < HID; k++) {
            float4 av  = ((const float4*)(sA + k * HID))[lane];
            float4 bvv = ((const float4*)(sB + k * HID))[lane];
            #pragma unroll
            for (int j = 0; j < 4; j++) {
                float a = myh[j * HID + k];
                aU[j].x = fmaf(a, av.x,  aU[j].x);
                aU[j].y = fmaf(a, av.y,  aU[j].y);
                aU[j].z = fmaf(a, av.z,  aU[j].z);
                aU[j].w = fmaf(a, av.w,  aU[j].w);
                aV[j].x = fmaf(a, bvv.x, aV[j].x);
                aV[j].y = fmaf(a, bvv.y, aV[j].y);
                aV[j].z = fmaf(a, bvv.z, aV[j].z);
                aV[j].w = fmaf(a, bvv.w, aV[j].w);
            }
        }
        #pragma unroll
        for (int j = 0; j < 4; j++) {
            int n = nbase + j;
            if (n < NN) {
                ((float4*)(g_U + (size_t)n * HID))[lane] = aU[j];
                ((float4*)(g_V + (size_t)n * HID))[lane] = aV[j];
            }
        }
    }
}

// ---------------- per-edge logit: relu(U[src]+V[dst]) . pW2 + pb2 ----------
__global__ void __launch_bounds__(256) pred_kernel(
    float* __restrict__ out,
    const float* __restrict__ pW2, const float* __restrict__ pb2)
{
    int lane = threadIdx.x & 31;
    int gw = (blockIdx.x * blockDim.x + threadIdx.x) >> 5;
    int nw = (gridDim.x * blockDim.x) >> 5;
    float4 wv = ((const float4*)pW2)[lane];
    float bias = __ldg(pb2);

    for (int e = gw; e < EE; e += nw) {
        int s = g_src[e], d = g_dst[e];
        float4 u = ((const float4*)(g_U + (size_t)s * HID))[lane];
        float4 v = ((const float4*)(g_V + (size_t)d * HID))[lane];
        float p = fmaxf(u.x + v.x, 0.f) * wv.x
                + fmaxf(u.y + v.y, 0.f) * wv.y
                + fmaxf(u.z + v.z, 0.f) * wv.z
                + fmaxf(u.w + v.w, 0.f) * wv.w;
        #pragma unroll
        for (int off = 16; off; off >>= 1)
            p += __shfl_xor_sync(0xffffffffu, p, off);
        if (lane == 0) out[e] = p + bias;
    }
}

// ---------------- launch ----------------------------------------------------
extern "C" void kernel_launch(void* const* d_in, const int* in_sizes, int n_in,
                              void* d_out, int out_size)
{
    const float* x   = (const float*)d_in[0];
    const void*  ei  = d_in[1];
    const float* ea  = (const float*)d_in[2];
    const float* eW  = (const float*)d_in[3];
    const float* eb  = (const float*)d_in[4];
    const float* W1  = (const float*)d_in[5];
    const float* b1  = (const float*)d_in[6];
    const float* W2  = (const float*)d_in[7];
    const float* b2  = (const float*)d_in[8];
    const float* pW1 = (const float*)d_in[9];
    const float* pb1 = (const float*)d_in[10];
    const float* pW2 = (const float*)d_in[11];
    const float* pb2 = (const float*)d_in[12];
    float* out = (float*)d_out;

    float *xb0, *xb1;
    cudaGetSymbolAddress((void**)&xb0, g_x0);
    cudaGetSymbolAddress((void**)&xb1, g_x1);

    const int EDGE_SMEM = (EIN * HID + HID + 64 * EIN) * 4;           // 49664 B
    const int NODE_SMEM = (2 * HID * HID + 2 * HID + 8 * 4 * HID) * 4; // 148480 B
    const int UV_SMEM   = (2 * HID * HID + HID + 8 * 4 * HID) * 4;     // 147968 B
    cudaFuncSetAttribute(edge_kernel, cudaFuncAttributeMaxDynamicSharedMemorySize, EDGE_SMEM);
    cudaFuncSetAttribute(node_kernel, cudaFuncAttributeMaxDynamicSharedMemorySize, NODE_SMEM);
    cudaFuncSetAttribute(uv_kernel,   cudaFuncAttributeMaxDynamicSharedMemorySize, UV_SMEM);

    init_flag_kernel<<<1, 1>>>();
    detect_kernel<<<256, 256>>>((const unsigned int*)ei);
    convert_kernel<<<1024, 256>>>(ei);

    const float* xin = x;
    for (int l = 0; l < 3; l++) {
        zero_aggr_kernel<<<800, 256>>>();
        edge_kernel<<<456, 256, EDGE_SMEM>>>(xin, ea,
                                             eW + (size_t)l * EIN * HID,
                                             eb + (size_t)l * HID);
        float* xout = (l & 1) ? xb1 : xb0;
        node_kernel<<<152, 256, NODE_SMEM>>>(xin,
                                             W1 + (size_t)l * HID * HID, b1 + (size_t)l * HID,
                                             W2 + (size_t)l * HID * HID, b2 + (size_t)l * HID,
                                             xout);
        xin = xout;
    }
    uv_kernel<<<152, 256, UV_SMEM>>>(xin, pW1, pb1);
    pred_kernel<<<2048, 256>>>(out, pW2, pb2);
}